// round 4
// baseline (speedup 1.0000x reference)
#include <cuda_runtime.h>
#include <cuda_bf16.h>
#include <cstdint>

#define NN 10000
#define NE 640000
#define D 128
#define H 8

// ---------------- scratch (no allocations allowed) ----------------
__device__ float g_Q[NN * D];
__device__ float g_K[NN * D];
__device__ float g_V[NN * D];
__device__ float g_wV[NN * D];
__device__ float g_z[NN * H];
// We in mma B-fragment layout: [img(hi/lo)][kb(8)][n8(16)][lane(32)] -> {b0,b1}
__device__ uint2 g_Bfrag[2][8][16][32];

__device__ __forceinline__ uint32_t smem_u32(const void* p) {
    uint32_t a;
    asm("{ .reg .u64 t; cvta.to.shared.u64 t, %1; cvt.u32.u64 %0, t; }" : "=r"(a) : "l"(p));
    return a;
}

#define LDSM4(r0, r1, r2, r3, a) \
    asm volatile("ldmatrix.sync.aligned.m8n8.x4.shared.b16 {%0,%1,%2,%3}, [%4];" \
        : "=r"(r0), "=r"(r1), "=r"(r2), "=r"(r3) : "r"(a))

#define MMA16816(c, a0, a1, a2, a3, b0, b1) \
    asm volatile("mma.sync.aligned.m16n8k16.row.col.f32.bf16.bf16.f32 " \
        "{%0,%1,%2,%3}, {%4,%5,%6,%7}, {%8,%9}, {%0,%1,%2,%3};" \
        : "+f"((c)[0]), "+f"((c)[1]), "+f"((c)[2]), "+f"((c)[3]) \
        : "r"(a0), "r"(a1), "r"(a2), "r"(a3), "r"(b0), "r"(b1))

// ---------------- zero accumulators ----------------
__global__ void zero_kernel() {
    int i = blockIdx.x * blockDim.x + threadIdx.x;
    if (i < NN * D) g_wV[i] = 0.f;
    if (i < NN * H) g_z[i] = 0.f;
}

// ---------------- prep B fragments: We[k][n] -> hi/lo bf16 fragment images ----------------
// b0: k = kb*16 + 2*(lane%4) + {0,1}, n = n8*8 + lane/4 ; b1: same k+8
__global__ void prep_Bfrag_kernel(const float* __restrict__ We) {
    int idx = blockIdx.x * 256 + threadIdx.x;   // 8192 entries
    if (idx >= 8192) return;
    int lane = idx & 31;
    int n8 = (idx >> 5) & 15;
    int kb = (idx >> 9) & 7;
    int img = idx >> 12;
    int n = n8 * 8 + (lane >> 2);
    int k0 = kb * 16 + 2 * (lane & 3);

    float f[4] = { We[k0 * 128 + n], We[(k0 + 1) * 128 + n],
                   We[(k0 + 8) * 128 + n], We[(k0 + 9) * 128 + n] };
    __nv_bfloat16 v[4];
#pragma unroll
    for (int j = 0; j < 4; ++j) {
        __nv_bfloat16 h = __float2bfloat16(f[j]);
        v[j] = img == 0 ? h : __float2bfloat16(f[j] - __bfloat162float(h));
    }
    __nv_bfloat162 p0(v[0], v[1]), p1(v[2], v[3]);
    g_Bfrag[img][kb][n8][lane] = make_uint2(*(uint32_t*)&p0, *(uint32_t*)&p1);
}

// ---------------- node projection GEMM (fp32, ~5% of work) ----------------
__global__ __launch_bounds__(256, 2)
void node_proj_kernel(const float* __restrict__ X,
                      const float* __restrict__ WQ,
                      const float* __restrict__ WK,
                      const float* __restrict__ WV) {
    const float* W = (blockIdx.y == 0) ? WQ : (blockIdx.y == 1) ? WK : WV;
    float* Out = (blockIdx.y == 0) ? g_Q : (blockIdx.y == 1) ? g_K : g_V;

    __shared__ float As[2][16][128];
    __shared__ float Bs[2][16][128];

    int tid = threadIdx.x;
    int ty = tid >> 4, tx = tid & 15;
    int rowBase = blockIdx.x << 7;

#pragma unroll
    for (int it = 0; it < 2; ++it) {
        int lin = tid + (it << 8);
        int r = lin >> 2, c4 = (lin & 3) << 2;
        int gr = rowBase + r; if (gr >= NN) gr = NN - 1;
        float4 v = *(const float4*)&X[(size_t)gr * D + c4];
        As[0][c4 + 0][r] = v.x; As[0][c4 + 1][r] = v.y;
        As[0][c4 + 2][r] = v.z; As[0][c4 + 3][r] = v.w;
        int kr = lin >> 5, b4 = (lin & 31) << 2;
        *(float4*)&Bs[0][kr][b4] = *(const float4*)&W[kr * D + b4];
    }
    __syncthreads();

    float acc[8][8];
#pragma unroll
    for (int i = 0; i < 8; ++i)
#pragma unroll
        for (int j = 0; j < 8; ++j) acc[i][j] = 0.f;

#pragma unroll
    for (int kt = 0; kt < 8; ++kt) {
        int cur = kt & 1;
        float4 rA[2], rB[2];
        if (kt < 7) {
            int kB = (kt + 1) << 4;
#pragma unroll
            for (int it = 0; it < 2; ++it) {
                int lin = tid + (it << 8);
                int r = lin >> 2, c4 = (lin & 3) << 2;
                int gr = rowBase + r; if (gr >= NN) gr = NN - 1;
                rA[it] = *(const float4*)&X[(size_t)gr * D + kB + c4];
                int kr = lin >> 5, b4 = (lin & 31) << 2;
                rB[it] = *(const float4*)&W[(kB + kr) * D + b4];
            }
        }
#pragma unroll
        for (int kk = 0; kk < 16; ++kk) {
            float a[8], b[8];
            *(float4*)&a[0] = *(const float4*)&As[cur][kk][ty << 3];
            *(float4*)&a[4] = *(const float4*)&As[cur][kk][(ty << 3) + 4];
            *(float4*)&b[0] = *(const float4*)&Bs[cur][kk][tx << 3];
            *(float4*)&b[4] = *(const float4*)&Bs[cur][kk][(tx << 3) + 4];
#pragma unroll
            for (int i = 0; i < 8; ++i)
#pragma unroll
                for (int j = 0; j < 8; ++j)
                    acc[i][j] = fmaf(a[i], b[j], acc[i][j]);
        }
        if (kt < 7) {
            int nxt = cur ^ 1;
#pragma unroll
            for (int it = 0; it < 2; ++it) {
                int lin = tid + (it << 8);
                int r = lin >> 2, c4 = (lin & 3) << 2;
                As[nxt][c4 + 0][r] = rA[it].x; As[nxt][c4 + 1][r] = rA[it].y;
                As[nxt][c4 + 2][r] = rA[it].z; As[nxt][c4 + 3][r] = rA[it].w;
                int kr = lin >> 5, b4 = (lin & 31) << 2;
                *(float4*)&Bs[nxt][kr][b4] = rB[it];
            }
            __syncthreads();
        }
    }

    int c0 = tx << 3;
#pragma unroll
    for (int i = 0; i < 8; ++i) {
        int gr = rowBase + (ty << 3) + i;
        if (gr < NN) {
            *(float4*)&Out[(size_t)gr * D + c0] =
                make_float4(acc[i][0], acc[i][1], acc[i][2], acc[i][3]);
            *(float4*)&Out[(size_t)gr * D + c0 + 4] =
                make_float4(acc[i][4], acc[i][5], acc[i][6], acc[i][7]);
        }
    }
}

// ---------------- fused edge kernel v2 ----------------
// TILE=128 edges, 8 warps in 2m x 4n grid (warp = 64 rows x 32 cols).
// A hi/lo in smem (XOR-swizzled 256B rows); B fragments LDG'd from global (L1/L2 resident).
// smem: [0] src[128], [512] dst[128], [1024] A_hi(32KB)+A_lo(32KB); Ds[128][132] aliases A.
#define SM_SRC  0
#define SM_DST  512
#define SM_A    1024
#define SM_ALO  (SM_A + 32768)
#define DS_PITCH 132
#define SM_EDGE_TOTAL (1024 + 128 * DS_PITCH * 4)   // 68608 > 1024+65536
#define TILE 128

__global__ __launch_bounds__(256, 2)
void edge_mma_kernel(const float* __restrict__ Ef,
                     const int* __restrict__ src, const int* __restrict__ dst,
                     float* __restrict__ e_out) {
    extern __shared__ char smem[];
    uint32_t sb = smem_u32(smem);
    int tid = threadIdx.x, wid = tid >> 5, lane = tid & 31;
    int rowBase = blockIdx.x << 7;

    if (tid < 128) {
        ((int*)(smem + SM_SRC))[tid] = src[rowBase + tid];
        ((int*)(smem + SM_DST))[tid] = dst[rowBase + tid];
    }

    // convert Ef tile (128 x 128 f32) -> bf16 hi/lo swizzled images
    {
        int row = tid >> 1, half = tid & 1;
        const float4* sp = (const float4*)&Ef[(size_t)(rowBase + row) * D + half * 64];
        uint32_t rbase = (uint32_t)(row * 256);
        int xr = row & 7;
#pragma unroll
        for (int i = 0; i < 8; ++i) {
            float4 v0 = sp[2 * i], v1 = sp[2 * i + 1];
            float f[8] = {v0.x, v0.y, v0.z, v0.w, v1.x, v1.y, v1.z, v1.w};
            __nv_bfloat16 h[8], l[8];
#pragma unroll
            for (int j = 0; j < 8; ++j) {
                h[j] = __float2bfloat16(f[j]);
                l[j] = __float2bfloat16(f[j] - __bfloat162float(h[j]));
            }
            int chunk = half * 8 + i;
            uint32_t off = rbase + (uint32_t)((chunk ^ xr) * 16);
            uint4 hv, lv;
            __nv_bfloat162 t;
            t = __nv_bfloat162(h[0], h[1]); hv.x = *(uint32_t*)&t;
            t = __nv_bfloat162(h[2], h[3]); hv.y = *(uint32_t*)&t;
            t = __nv_bfloat162(h[4], h[5]); hv.z = *(uint32_t*)&t;
            t = __nv_bfloat162(h[6], h[7]); hv.w = *(uint32_t*)&t;
            t = __nv_bfloat162(l[0], l[1]); lv.x = *(uint32_t*)&t;
            t = __nv_bfloat162(l[2], l[3]); lv.y = *(uint32_t*)&t;
            t = __nv_bfloat162(l[4], l[5]); lv.z = *(uint32_t*)&t;
            t = __nv_bfloat162(l[6], l[7]); lv.w = *(uint32_t*)&t;
            *(uint4*)(smem + SM_A + off) = hv;
            *(uint4*)(smem + SM_ALO + off) = lv;
        }
    }
    __syncthreads();

    // ---- MMA: warp (wm, wn): rows wm*64..+63, n8 blocks wn*4..+3 ----
    int wm = wid >> 2, wn = wid & 3;
    float c[4][4][4];
#pragma unroll
    for (int m = 0; m < 4; ++m)
#pragma unroll
        for (int n = 0; n < 4; ++n)
#pragma unroll
            for (int j = 0; j < 4; ++j) c[m][n][j] = 0.f;

    int ar = (lane & 7) + ((lane >> 3) & 1) * 8;   // row within m16
    int aco = lane >> 4;                           // k16-half chunk
    int axr = lane & 7;
    uint32_t aBase = sb + (uint32_t)((wm * 64 + ar) * 256);

#pragma unroll
    for (int kb = 0; kb < 8; ++kb) {
        uint32_t au = (uint32_t)((2 * kb + aco) ^ axr) * 16;
        uint32_t Ah[4][4];
#pragma unroll
        for (int m = 0; m < 4; ++m)
            LDSM4(Ah[m][0], Ah[m][1], Ah[m][2], Ah[m][3], aBase + SM_A + (uint32_t)(m * 16 * 256) + au);

        uint2 Bh[4], Bl[4];
#pragma unroll
        for (int n = 0; n < 4; ++n) Bh[n] = g_Bfrag[0][kb][wn * 4 + n][lane];
#pragma unroll
        for (int m = 0; m < 4; ++m)
#pragma unroll
            for (int n = 0; n < 4; ++n)
                MMA16816(c[m][n], Ah[m][0], Ah[m][1], Ah[m][2], Ah[m][3], Bh[n].x, Bh[n].y);

#pragma unroll
        for (int n = 0; n < 4; ++n) Bl[n] = g_Bfrag[1][kb][wn * 4 + n][lane];
#pragma unroll
        for (int m = 0; m < 4; ++m)
#pragma unroll
            for (int n = 0; n < 4; ++n)
                MMA16816(c[m][n], Ah[m][0], Ah[m][1], Ah[m][2], Ah[m][3], Bl[n].x, Bl[n].y);

#pragma unroll
        for (int m = 0; m < 4; ++m)
            LDSM4(Ah[m][0], Ah[m][1], Ah[m][2], Ah[m][3], aBase + SM_ALO + (uint32_t)(m * 16 * 256) + au);
#pragma unroll
        for (int m = 0; m < 4; ++m)
#pragma unroll
            for (int n = 0; n < 4; ++n)
                MMA16816(c[m][n], Ah[m][0], Ah[m][1], Ah[m][2], Ah[m][3], Bh[n].x, Bh[n].y);
    }

    __syncthreads();   // all A reads done before Ds aliases the region

    // stage C -> Ds[128][132]
    float* Ds = (float*)(smem + SM_A);
    {
        int rq = lane >> 2, cq = (lane & 3) * 2;
#pragma unroll
        for (int m = 0; m < 4; ++m) {
            int r0 = wm * 64 + m * 16 + rq;
#pragma unroll
            for (int n = 0; n < 4; ++n) {
                int cc = (wn * 4 + n) * 8 + cq;
                *(float2*)&Ds[r0 * DS_PITCH + cc] = make_float2(c[m][n][0], c[m][n][1]);
                *(float2*)&Ds[(r0 + 8) * DS_PITCH + cc] = make_float2(c[m][n][2], c[m][n][3]);
            }
        }
    }
    __syncthreads();

    // ---- epilogue (proven coalesced layout), 128 rows ----
    const float isd = 0.25f;
    int ty = tid >> 4, tx = tid & 15;
    int c0 = tx << 3;
    int h = tx >> 1;
    const int* s_src = (const int*)(smem + SM_SRC);
    const int* s_dst = (const int*)(smem + SM_DST);

#pragma unroll
    for (int i = 0; i < 8; ++i) {
        int er = ty * 8 + i;
        int e = rowBase + er;
        int sn = s_src[er], dn = s_dst[er];

        float4 k0 = *(const float4*)&g_K[sn * D + c0];
        float4 k1 = *(const float4*)&g_K[sn * D + c0 + 4];
        float4 q0 = *(const float4*)&g_Q[dn * D + c0];
        float4 q1 = *(const float4*)&g_Q[dn * D + c0 + 4];

        float kq[8];
        kq[0] = k0.x * q0.x; kq[1] = k0.y * q0.y; kq[2] = k0.z * q0.z; kq[3] = k0.w * q0.w;
        kq[4] = k1.x * q1.x; kq[5] = k1.y * q1.y; kq[6] = k1.z * q1.z; kq[7] = k1.w * q1.w;

        float pe[8];
        *(float4*)&pe[0] = *(const float4*)&Ds[er * DS_PITCH + c0];
        *(float4*)&pe[4] = *(const float4*)&Ds[er * DS_PITCH + c0 + 4];

        float sc[8];
        float part = 0.f;
#pragma unroll
        for (int j = 0; j < 8; ++j) {
            float t = fminf(fmaxf(kq[j] * isd, -5.f), 5.f);
            sc[j] = t * pe[j];
            part += sc[j];
        }

        *(float4*)&e_out[(size_t)e * D + c0] = make_float4(sc[0], sc[1], sc[2], sc[3]);
        *(float4*)&e_out[(size_t)e * D + c0 + 4] = make_float4(sc[4], sc[5], sc[6], sc[7]);

        float tot = part + __shfl_xor_sync(0xffffffffu, part, 1);
        float s = __expf(fminf(fmaxf(tot, -5.f), 5.f));

        float4 v0 = *(const float4*)&g_V[sn * D + c0];
        float4 v1 = *(const float4*)&g_V[sn * D + c0 + 4];
        float* w = &g_wV[dn * D + c0];
        asm volatile("red.global.add.v4.f32 [%0], {%1,%2,%3,%4};"
                     :: "l"(w), "f"(v0.x * s), "f"(v0.y * s), "f"(v0.z * s), "f"(v0.w * s)
                     : "memory");
        asm volatile("red.global.add.v4.f32 [%0], {%1,%2,%3,%4};"
                     :: "l"(w + 4), "f"(v1.x * s), "f"(v1.y * s), "f"(v1.z * s), "f"(v1.w * s)
                     : "memory");
        if ((tx & 1) == 0)
            atomicAdd(&g_z[dn * H + h], s);
    }
}

// ---------------- normalize ----------------
__global__ void norm_kernel(float* __restrict__ h_out) {
    int i = blockIdx.x * blockDim.x + threadIdx.x;
    if (i < NN * D) {
        int n = i >> 7;
        int hh = (i & 127) >> 4;
        h_out[i] = g_wV[i] / (g_z[n * H + hh] + 1e-6f);
    }
}

// ---------------- launch ----------------
extern "C" void kernel_launch(void* const* d_in, const int* in_sizes, int n_in,
                              void* d_out, int out_size) {
    const float* node_feats = (const float*)d_in[0];
    const float* edge_feats = (const float*)d_in[1];
    const int* src = (const int*)d_in[2];
    const int* dst = (const int*)d_in[3];
    const float* WQ = (const float*)d_in[4];
    const float* WK = (const float*)d_in[5];
    const float* WV = (const float*)d_in[6];
    const float* We = (const float*)d_in[7];

    float* out = (float*)d_out;
    float* h_out = out;                  // [NN, H, DH]
    float* e_out = out + (size_t)NN * D; // [NE, H, DH]

    static int smem_set = 0;
    if (!smem_set) {
        cudaFuncSetAttribute(edge_mma_kernel, cudaFuncAttributeMaxDynamicSharedMemorySize, SM_EDGE_TOTAL);
        smem_set = 1;
    }

    zero_kernel<<<(NN * D + 255) / 256, 256>>>();
    prep_Bfrag_kernel<<<32, 256>>>(We);

    dim3 gn((NN + 127) / 128, 3);
    node_proj_kernel<<<gn, 256>>>(node_feats, WQ, WK, WV);

    edge_mma_kernel<<<NE / TILE, 256, SM_EDGE_TOTAL>>>(edge_feats, src, dst, e_out);

    norm_kernel<<<(NN * D + 255) / 256, 256>>>(h_out);
}

// round 5
// speedup vs baseline: 1.8438x; 1.8438x over previous
#include <cuda_runtime.h>
#include <cuda_bf16.h>
#include <cstdint>

#define NN 10000
#define NE 640000
#define D 128
#define H 8

// ---------------- scratch (no allocations allowed) ----------------
__device__ float g_Q[NN * D];
__device__ float g_K[NN * D];
__device__ float g_V[NN * D];
__device__ float g_wV[NN * D];
__device__ float g_z[NN * H];
// We in mma B-fragment layout: [img(hi/lo)][kb(8)][n8(16)][lane(32)] -> {b0,b1}
__device__ uint2 g_Bfrag[2][8][16][32];

__device__ __forceinline__ uint32_t smem_u32(const void* p) {
    uint32_t a;
    asm("{ .reg .u64 t; cvta.to.shared.u64 t, %1; cvt.u32.u64 %0, t; }" : "=r"(a) : "l"(p));
    return a;
}

#define LDSM4(r0, r1, r2, r3, a) \
    asm volatile("ldmatrix.sync.aligned.m8n8.x4.shared.b16 {%0,%1,%2,%3}, [%4];" \
        : "=r"(r0), "=r"(r1), "=r"(r2), "=r"(r3) : "r"(a))

#define MMA16816(c, a0, a1, a2, a3, b0, b1) \
    asm volatile("mma.sync.aligned.m16n8k16.row.col.f32.bf16.bf16.f32 " \
        "{%0,%1,%2,%3}, {%4,%5,%6,%7}, {%8,%9}, {%0,%1,%2,%3};" \
        : "+f"((c)[0]), "+f"((c)[1]), "+f"((c)[2]), "+f"((c)[3]) \
        : "r"(a0), "r"(a1), "r"(a2), "r"(a3), "r"(b0), "r"(b1))

// ---------------- zero accumulators ----------------
__global__ void zero_kernel() {
    int i = blockIdx.x * blockDim.x + threadIdx.x;
    if (i < NN * D) g_wV[i] = 0.f;
    if (i < NN * H) g_z[i] = 0.f;
}

// ---------------- prep B fragments: We[k][n] -> hi/lo bf16 fragment images ----------------
__global__ void prep_Bfrag_kernel(const float* __restrict__ We) {
    int idx = blockIdx.x * 256 + threadIdx.x;   // 8192 entries
    if (idx >= 8192) return;
    int lane = idx & 31;
    int n8 = (idx >> 5) & 15;
    int kb = (idx >> 9) & 7;
    int img = idx >> 12;
    int n = n8 * 8 + (lane >> 2);
    int k0 = kb * 16 + 2 * (lane & 3);

    float f[4] = { We[k0 * 128 + n], We[(k0 + 1) * 128 + n],
                   We[(k0 + 8) * 128 + n], We[(k0 + 9) * 128 + n] };
    __nv_bfloat16 v[4];
#pragma unroll
    for (int j = 0; j < 4; ++j) {
        __nv_bfloat16 h = __float2bfloat16(f[j]);
        v[j] = img == 0 ? h : __float2bfloat16(f[j] - __bfloat162float(h));
    }
    __nv_bfloat162 p0(v[0], v[1]), p1(v[2], v[3]);
    g_Bfrag[img][kb][n8][lane] = make_uint2(*(uint32_t*)&p0, *(uint32_t*)&p1);
}

// ---------------- node projection GEMM (fp32, ~5% of work) ----------------
__global__ __launch_bounds__(256, 2)
void node_proj_kernel(const float* __restrict__ X,
                      const float* __restrict__ WQ,
                      const float* __restrict__ WK,
                      const float* __restrict__ WV) {
    const float* W = (blockIdx.y == 0) ? WQ : (blockIdx.y == 1) ? WK : WV;
    float* Out = (blockIdx.y == 0) ? g_Q : (blockIdx.y == 1) ? g_K : g_V;

    __shared__ float As[2][16][128];
    __shared__ float Bs[2][16][128];

    int tid = threadIdx.x;
    int ty = tid >> 4, tx = tid & 15;
    int rowBase = blockIdx.x << 7;

#pragma unroll
    for (int it = 0; it < 2; ++it) {
        int lin = tid + (it << 8);
        int r = lin >> 2, c4 = (lin & 3) << 2;
        int gr = rowBase + r; if (gr >= NN) gr = NN - 1;
        float4 v = *(const float4*)&X[(size_t)gr * D + c4];
        As[0][c4 + 0][r] = v.x; As[0][c4 + 1][r] = v.y;
        As[0][c4 + 2][r] = v.z; As[0][c4 + 3][r] = v.w;
        int kr = lin >> 5, b4 = (lin & 31) << 2;
        *(float4*)&Bs[0][kr][b4] = *(const float4*)&W[kr * D + b4];
    }
    __syncthreads();

    float acc[8][8];
#pragma unroll
    for (int i = 0; i < 8; ++i)
#pragma unroll
        for (int j = 0; j < 8; ++j) acc[i][j] = 0.f;

#pragma unroll
    for (int kt = 0; kt < 8; ++kt) {
        int cur = kt & 1;
        float4 rA[2], rB[2];
        if (kt < 7) {
            int kB = (kt + 1) << 4;
#pragma unroll
            for (int it = 0; it < 2; ++it) {
                int lin = tid + (it << 8);
                int r = lin >> 2, c4 = (lin & 3) << 2;
                int gr = rowBase + r; if (gr >= NN) gr = NN - 1;
                rA[it] = *(const float4*)&X[(size_t)gr * D + kB + c4];
                int kr = lin >> 5, b4 = (lin & 31) << 2;
                rB[it] = *(const float4*)&W[(kB + kr) * D + b4];
            }
        }
#pragma unroll
        for (int kk = 0; kk < 16; ++kk) {
            float a[8], b[8];
            *(float4*)&a[0] = *(const float4*)&As[cur][kk][ty << 3];
            *(float4*)&a[4] = *(const float4*)&As[cur][kk][(ty << 3) + 4];
            *(float4*)&b[0] = *(const float4*)&Bs[cur][kk][tx << 3];
            *(float4*)&b[4] = *(const float4*)&Bs[cur][kk][(tx << 3) + 4];
#pragma unroll
            for (int i = 0; i < 8; ++i)
#pragma unroll
                for (int j = 0; j < 8; ++j)
                    acc[i][j] = fmaf(a[i], b[j], acc[i][j]);
        }
        if (kt < 7) {
            int nxt = cur ^ 1;
#pragma unroll
            for (int it = 0; it < 2; ++it) {
                int lin = tid + (it << 8);
                int r = lin >> 2, c4 = (lin & 3) << 2;
                As[nxt][c4 + 0][r] = rA[it].x; As[nxt][c4 + 1][r] = rA[it].y;
                As[nxt][c4 + 2][r] = rA[it].z; As[nxt][c4 + 3][r] = rA[it].w;
                int kr = lin >> 5, b4 = (lin & 31) << 2;
                *(float4*)&Bs[nxt][kr][b4] = rB[it];
            }
            __syncthreads();
        }
    }

    int c0 = tx << 3;
#pragma unroll
    for (int i = 0; i < 8; ++i) {
        int gr = rowBase + (ty << 3) + i;
        if (gr < NN) {
            *(float4*)&Out[(size_t)gr * D + c0] =
                make_float4(acc[i][0], acc[i][1], acc[i][2], acc[i][3]);
            *(float4*)&Out[(size_t)gr * D + c0 + 4] =
                make_float4(acc[i][4], acc[i][5], acc[i][6], acc[i][7]);
        }
    }
}

// ---------------- fused edge kernel v3: wavefront-optimal convert ----------------
// TILE=128 edges, 8 warps in 2m x 4n grid (warp = 64 rows x 32 cols).
// A hi/lo in smem (XOR-swizzled 256B rows); B fragments LDG'd from global (L1/L2 resident).
// smem: [0] src[128], [512] dst[128], [1024] A_hi(32KB)+A_lo(32KB); Ds[128][132] aliases A.
#define SM_SRC  0
#define SM_DST  512
#define SM_A    1024
#define SM_ALO  (SM_A + 32768)
#define DS_PITCH 132
#define SM_EDGE_TOTAL (1024 + 128 * DS_PITCH * 4)   // 68608 > 1024+65536
#define TILE 128

__global__ __launch_bounds__(256, 2)
void edge_mma_kernel(const float* __restrict__ Ef,
                     const int* __restrict__ src, const int* __restrict__ dst,
                     float* __restrict__ e_out) {
    extern __shared__ char smem[];
    uint32_t sb = smem_u32(smem);
    int tid = threadIdx.x, wid = tid >> 5, lane = tid & 31;
    int rowBase = blockIdx.x << 7;

    if (tid < 128) {
        ((int*)(smem + SM_SRC))[tid] = src[rowBase + tid];
        ((int*)(smem + SM_DST))[tid] = dst[rowBase + tid];
    }

    // convert Ef tile (128 x 128 f32) -> bf16 hi/lo swizzled images.
    // warp owns 16 rows; per row one coalesced LDG.128 (4 wavefronts) + 2-phase STS.64s.
    {
        int row0 = wid * 16;
        int chunk = lane >> 1, half = lane & 1;
#pragma unroll
        for (int r4 = 0; r4 < 4; ++r4) {
            float4 v[4];
#pragma unroll
            for (int j = 0; j < 4; ++j) {
                int row = row0 + r4 * 4 + j;
                v[j] = __ldcs((const float4*)&Ef[(size_t)(rowBase + row) * D + lane * 4]);
            }
#pragma unroll
            for (int j = 0; j < 4; ++j) {
                int row = row0 + r4 * 4 + j;
                float f[4] = {v[j].x, v[j].y, v[j].z, v[j].w};
                __nv_bfloat16 h[4], l[4];
#pragma unroll
                for (int t = 0; t < 4; ++t) {
                    h[t] = __float2bfloat16(f[t]);
                    l[t] = __float2bfloat16(f[t] - __bfloat162float(h[t]));
                }
                __nv_bfloat162 hp0(h[0], h[1]), hp1(h[2], h[3]);
                __nv_bfloat162 lp0(l[0], l[1]), lp1(l[2], l[3]);
                uint32_t off = (uint32_t)(row * 256 + ((chunk ^ (row & 7)) * 16) + half * 8);
                *(uint2*)(smem + SM_A + off) = make_uint2(*(uint32_t*)&hp0, *(uint32_t*)&hp1);
                *(uint2*)(smem + SM_ALO + off) = make_uint2(*(uint32_t*)&lp0, *(uint32_t*)&lp1);
            }
        }
    }
    __syncthreads();

    // ---- MMA: warp (wm, wn): rows wm*64..+63, n8 blocks wn*4..+3 ----
    int wm = wid >> 2, wn = wid & 3;
    float c[4][4][4];
#pragma unroll
    for (int m = 0; m < 4; ++m)
#pragma unroll
        for (int n = 0; n < 4; ++n)
#pragma unroll
            for (int j = 0; j < 4; ++j) c[m][n][j] = 0.f;

    int ar = (lane & 7) + ((lane >> 3) & 1) * 8;   // row within m16
    int aco = lane >> 4;                           // k16-half chunk
    int axr = lane & 7;
    uint32_t aBase = sb + (uint32_t)((wm * 64 + ar) * 256);

#pragma unroll
    for (int kb = 0; kb < 8; ++kb) {
        uint32_t au = (uint32_t)((2 * kb + aco) ^ axr) * 16;
        uint32_t Ah[4][4];
#pragma unroll
        for (int m = 0; m < 4; ++m)
            LDSM4(Ah[m][0], Ah[m][1], Ah[m][2], Ah[m][3], aBase + SM_A + (uint32_t)(m * 16 * 256) + au);

        uint2 Bh[4], Bl[4];
#pragma unroll
        for (int n = 0; n < 4; ++n) Bh[n] = g_Bfrag[0][kb][wn * 4 + n][lane];
#pragma unroll
        for (int m = 0; m < 4; ++m)
#pragma unroll
            for (int n = 0; n < 4; ++n)
                MMA16816(c[m][n], Ah[m][0], Ah[m][1], Ah[m][2], Ah[m][3], Bh[n].x, Bh[n].y);

#pragma unroll
        for (int n = 0; n < 4; ++n) Bl[n] = g_Bfrag[1][kb][wn * 4 + n][lane];
#pragma unroll
        for (int m = 0; m < 4; ++m)
#pragma unroll
            for (int n = 0; n < 4; ++n)
                MMA16816(c[m][n], Ah[m][0], Ah[m][1], Ah[m][2], Ah[m][3], Bl[n].x, Bl[n].y);

#pragma unroll
        for (int m = 0; m < 4; ++m)
            LDSM4(Ah[m][0], Ah[m][1], Ah[m][2], Ah[m][3], aBase + SM_ALO + (uint32_t)(m * 16 * 256) + au);
#pragma unroll
        for (int m = 0; m < 4; ++m)
#pragma unroll
            for (int n = 0; n < 4; ++n)
                MMA16816(c[m][n], Ah[m][0], Ah[m][1], Ah[m][2], Ah[m][3], Bh[n].x, Bh[n].y);
    }

    __syncthreads();   // all A reads done before Ds aliases the region

    // stage C -> Ds[128][132]
    float* Ds = (float*)(smem + SM_A);
    {
        int rq = lane >> 2, cq = (lane & 3) * 2;
#pragma unroll
        for (int m = 0; m < 4; ++m) {
            int r0 = wm * 64 + m * 16 + rq;
#pragma unroll
            for (int n = 0; n < 4; ++n) {
                int cc = (wn * 4 + n) * 8 + cq;
                *(float2*)&Ds[r0 * DS_PITCH + cc] = make_float2(c[m][n][0], c[m][n][1]);
                *(float2*)&Ds[(r0 + 8) * DS_PITCH + cc] = make_float2(c[m][n][2], c[m][n][3]);
            }
        }
    }
    __syncthreads();

    // ---- epilogue (proven coalesced layout), 128 rows ----
    const float isd = 0.25f;
    int ty = tid >> 4, tx = tid & 15;
    int c0 = tx << 3;
    int h = tx >> 1;
    const int* s_src = (const int*)(smem + SM_SRC);
    const int* s_dst = (const int*)(smem + SM_DST);

#pragma unroll
    for (int i = 0; i < 8; ++i) {
        int er = ty * 8 + i;
        int e = rowBase + er;
        int sn = s_src[er], dn = s_dst[er];

        float4 k0 = *(const float4*)&g_K[sn * D + c0];
        float4 k1 = *(const float4*)&g_K[sn * D + c0 + 4];
        float4 q0 = *(const float4*)&g_Q[dn * D + c0];
        float4 q1 = *(const float4*)&g_Q[dn * D + c0 + 4];

        float kq[8];
        kq[0] = k0.x * q0.x; kq[1] = k0.y * q0.y; kq[2] = k0.z * q0.z; kq[3] = k0.w * q0.w;
        kq[4] = k1.x * q1.x; kq[5] = k1.y * q1.y; kq[6] = k1.z * q1.z; kq[7] = k1.w * q1.w;

        float pe[8];
        *(float4*)&pe[0] = *(const float4*)&Ds[er * DS_PITCH + c0];
        *(float4*)&pe[4] = *(const float4*)&Ds[er * DS_PITCH + c0 + 4];

        float sc[8];
        float part = 0.f;
#pragma unroll
        for (int j = 0; j < 8; ++j) {
            float t = fminf(fmaxf(kq[j] * isd, -5.f), 5.f);
            sc[j] = t * pe[j];
            part += sc[j];
        }

        __stcs((float4*)&e_out[(size_t)e * D + c0],
               make_float4(sc[0], sc[1], sc[2], sc[3]));
        __stcs((float4*)&e_out[(size_t)e * D + c0 + 4],
               make_float4(sc[4], sc[5], sc[6], sc[7]));

        float tot = part + __shfl_xor_sync(0xffffffffu, part, 1);
        float s = __expf(fminf(fmaxf(tot, -5.f), 5.f));

        float4 v0 = *(const float4*)&g_V[sn * D + c0];
        float4 v1 = *(const float4*)&g_V[sn * D + c0 + 4];
        float* w = &g_wV[dn * D + c0];
        asm volatile("red.global.add.v4.f32 [%0], {%1,%2,%3,%4};"
                     :: "l"(w), "f"(v0.x * s), "f"(v0.y * s), "f"(v0.z * s), "f"(v0.w * s)
                     : "memory");
        asm volatile("red.global.add.v4.f32 [%0], {%1,%2,%3,%4};"
                     :: "l"(w + 4), "f"(v1.x * s), "f"(v1.y * s), "f"(v1.z * s), "f"(v1.w * s)
                     : "memory");
        if ((tx & 1) == 0)
            atomicAdd(&g_z[dn * H + h], s);
    }
}

// ---------------- normalize ----------------
__global__ void norm_kernel(float* __restrict__ h_out) {
    int i = blockIdx.x * blockDim.x + threadIdx.x;
    if (i < NN * D) {
        int n = i >> 7;
        int hh = (i & 127) >> 4;
        h_out[i] = g_wV[i] / (g_z[n * H + hh] + 1e-6f);
    }
}

// ---------------- launch ----------------
extern "C" void kernel_launch(void* const* d_in, const int* in_sizes, int n_in,
                              void* d_out, int out_size) {
    const float* node_feats = (const float*)d_in[0];
    const float* edge_feats = (const float*)d_in[1];
    const int* src = (const int*)d_in[2];
    const int* dst = (const int*)d_in[3];
    const float* WQ = (const float*)d_in[4];
    const float* WK = (const float*)d_in[5];
    const float* WV = (const float*)d_in[6];
    const float* We = (const float*)d_in[7];

    float* out = (float*)d_out;
    float* h_out = out;                  // [NN, H, DH]
    float* e_out = out + (size_t)NN * D; // [NE, H, DH]

    static int smem_set = 0;
    if (!smem_set) {
        cudaFuncSetAttribute(edge_mma_kernel, cudaFuncAttributeMaxDynamicSharedMemorySize, SM_EDGE_TOTAL);
        smem_set = 1;
    }

    zero_kernel<<<(NN * D + 255) / 256, 256>>>();
    prep_Bfrag_kernel<<<32, 256>>>(We);

    dim3 gn((NN + 127) / 128, 3);
    node_proj_kernel<<<gn, 256>>>(node_feats, WQ, WK, WV);

    edge_mma_kernel<<<NE / TILE, 256, SM_EDGE_TOTAL>>>(edge_feats, src, dst, e_out);

    norm_kernel<<<(NN * D + 255) / 256, 256>>>(h_out);
}

// round 6
// speedup vs baseline: 2.3822x; 1.2920x over previous
#include <cuda_runtime.h>
#include <cuda_fp16.h>
#include <cstdint>

#define NN 10000
#define NE 640000
#define D 128
#define H 8

// ---------------- scratch (no allocations allowed) ----------------
__device__ float g_Q[NN * D];
__device__ float g_K[NN * D];
__device__ float g_V[NN * D];
__device__ float g_wV[NN * D];
__device__ float g_z[NN * H];
// We in mma B-fragment layout (fp16): [kb(8)][n8(16)][lane(32)] -> {b0,b1}
__device__ uint2 g_Bfrag[8][16][32];

__device__ __forceinline__ uint32_t smem_u32(const void* p) {
    uint32_t a;
    asm("{ .reg .u64 t; cvta.to.shared.u64 t, %1; cvt.u32.u64 %0, t; }" : "=r"(a) : "l"(p));
    return a;
}

#define LDSM4(r0, r1, r2, r3, a) \
    asm volatile("ldmatrix.sync.aligned.m8n8.x4.shared.b16 {%0,%1,%2,%3}, [%4];" \
        : "=r"(r0), "=r"(r1), "=r"(r2), "=r"(r3) : "r"(a))

#define MMA16816(c, a0, a1, a2, a3, b0, b1) \
    asm volatile("mma.sync.aligned.m16n8k16.row.col.f32.f16.f16.f32 " \
        "{%0,%1,%2,%3}, {%4,%5,%6,%7}, {%8,%9}, {%0,%1,%2,%3};" \
        : "+f"((c)[0]), "+f"((c)[1]), "+f"((c)[2]), "+f"((c)[3]) \
        : "r"(a0), "r"(a1), "r"(a2), "r"(a3), "r"(b0), "r"(b1))

// ---------------- zero accumulators ----------------
__global__ void zero_kernel() {
    int i = blockIdx.x * blockDim.x + threadIdx.x;
    if (i < NN * D) g_wV[i] = 0.f;
    if (i < NN * H) g_z[i] = 0.f;
}

// ---------------- prep B fragments: We[k][n] -> fp16 fragment image ----------------
__global__ void prep_Bfrag_kernel(const float* __restrict__ We) {
    int idx = blockIdx.x * 256 + threadIdx.x;   // 4096 entries
    if (idx >= 4096) return;
    int lane = idx & 31;
    int n8 = (idx >> 5) & 15;
    int kb = (idx >> 9) & 7;
    int n = n8 * 8 + (lane >> 2);
    int k0 = kb * 16 + 2 * (lane & 3);

    __half2 p0 = __halves2half2(__float2half(We[k0 * 128 + n]),
                                __float2half(We[(k0 + 1) * 128 + n]));
    __half2 p1 = __halves2half2(__float2half(We[(k0 + 8) * 128 + n]),
                                __float2half(We[(k0 + 9) * 128 + n]));
    g_Bfrag[kb][n8][lane] = make_uint2(*(uint32_t*)&p0, *(uint32_t*)&p1);
}

// ---------------- node projection GEMM (fp32, ~5% of work) ----------------
__global__ __launch_bounds__(256, 2)
void node_proj_kernel(const float* __restrict__ X,
                      const float* __restrict__ WQ,
                      const float* __restrict__ WK,
                      const float* __restrict__ WV) {
    const float* W = (blockIdx.y == 0) ? WQ : (blockIdx.y == 1) ? WK : WV;
    float* Out = (blockIdx.y == 0) ? g_Q : (blockIdx.y == 1) ? g_K : g_V;

    __shared__ float As[2][16][128];
    __shared__ float Bs[2][16][128];

    int tid = threadIdx.x;
    int ty = tid >> 4, tx = tid & 15;
    int rowBase = blockIdx.x << 7;

#pragma unroll
    for (int it = 0; it < 2; ++it) {
        int lin = tid + (it << 8);
        int r = lin >> 2, c4 = (lin & 3) << 2;
        int gr = rowBase + r; if (gr >= NN) gr = NN - 1;
        float4 v = *(const float4*)&X[(size_t)gr * D + c4];
        As[0][c4 + 0][r] = v.x; As[0][c4 + 1][r] = v.y;
        As[0][c4 + 2][r] = v.z; As[0][c4 + 3][r] = v.w;
        int kr = lin >> 5, b4 = (lin & 31) << 2;
        *(float4*)&Bs[0][kr][b4] = *(const float4*)&W[kr * D + b4];
    }
    __syncthreads();

    float acc[8][8];
#pragma unroll
    for (int i = 0; i < 8; ++i)
#pragma unroll
        for (int j = 0; j < 8; ++j) acc[i][j] = 0.f;

#pragma unroll
    for (int kt = 0; kt < 8; ++kt) {
        int cur = kt & 1;
        float4 rA[2], rB[2];
        if (kt < 7) {
            int kB = (kt + 1) << 4;
#pragma unroll
            for (int it = 0; it < 2; ++it) {
                int lin = tid + (it << 8);
                int r = lin >> 2, c4 = (lin & 3) << 2;
                int gr = rowBase + r; if (gr >= NN) gr = NN - 1;
                rA[it] = *(const float4*)&X[(size_t)gr * D + kB + c4];
                int kr = lin >> 5, b4 = (lin & 31) << 2;
                rB[it] = *(const float4*)&W[(kB + kr) * D + b4];
            }
        }
#pragma unroll
        for (int kk = 0; kk < 16; ++kk) {
            float a[8], b[8];
            *(float4*)&a[0] = *(const float4*)&As[cur][kk][ty << 3];
            *(float4*)&a[4] = *(const float4*)&As[cur][kk][(ty << 3) + 4];
            *(float4*)&b[0] = *(const float4*)&Bs[cur][kk][tx << 3];
            *(float4*)&b[4] = *(const float4*)&Bs[cur][kk][(tx << 3) + 4];
#pragma unroll
            for (int i = 0; i < 8; ++i)
#pragma unroll
                for (int j = 0; j < 8; ++j)
                    acc[i][j] = fmaf(a[i], b[j], acc[i][j]);
        }
        if (kt < 7) {
            int nxt = cur ^ 1;
#pragma unroll
            for (int it = 0; it < 2; ++it) {
                int lin = tid + (it << 8);
                int r = lin >> 2, c4 = (lin & 3) << 2;
                As[nxt][c4 + 0][r] = rA[it].x; As[nxt][c4 + 1][r] = rA[it].y;
                As[nxt][c4 + 2][r] = rA[it].z; As[nxt][c4 + 3][r] = rA[it].w;
                int kr = lin >> 5, b4 = (lin & 31) << 2;
                *(float4*)&Bs[nxt][kr][b4] = rB[it];
            }
            __syncthreads();
        }
    }

    int c0 = tx << 3;
#pragma unroll
    for (int i = 0; i < 8; ++i) {
        int gr = rowBase + (ty << 3) + i;
        if (gr < NN) {
            *(float4*)&Out[(size_t)gr * D + c0] =
                make_float4(acc[i][0], acc[i][1], acc[i][2], acc[i][3]);
            *(float4*)&Out[(size_t)gr * D + c0 + 4] =
                make_float4(acc[i][4], acc[i][5], acc[i][6], acc[i][7]);
        }
    }
}

// ---------------- fused edge kernel v4: fp16 single-pass, 512 threads ----------------
// TILE=128 edges, 16 warps in 4m x 4n grid (warp = 32 rows x 32 cols).
// A fp16 in smem (XOR-swizzled 256B rows); B fragments LDG'd from global (L1/L2 resident).
// smem: [0] src[128], [512] dst[128], [1024] A(32KB); Ds[128][132] f32 aliases A after MMA.
#define SM_SRC  0
#define SM_DST  512
#define SM_A    1024
#define DS_PITCH 132
#define SM_EDGE_TOTAL (1024 + 128 * DS_PITCH * 4)   // 68608
#define TILE 128

__global__ __launch_bounds__(512, 2)
void edge_mma_kernel(const float* __restrict__ Ef,
                     const int* __restrict__ src, const int* __restrict__ dst,
                     float* __restrict__ e_out) {
    extern __shared__ char smem[];
    uint32_t sb = smem_u32(smem);
    int tid = threadIdx.x, wid = tid >> 5, lane = tid & 31;
    int rowBase = blockIdx.x << 7;

    if (tid < 128) {
        ((int*)(smem + SM_SRC))[tid] = src[rowBase + tid];
        ((int*)(smem + SM_DST))[tid] = dst[rowBase + tid];
    }

    // convert Ef tile (128 x 128 f32) -> fp16 swizzled image.
    // warp owns 8 rows; per row one coalesced LDG.128 + 2-phase STS.64.
    {
        int row0 = wid * 8;
        int chunk = lane >> 1, half = lane & 1;
#pragma unroll
        for (int j = 0; j < 8; ++j) {
            int row = row0 + j;
            float4 v = __ldcs((const float4*)&Ef[(size_t)(rowBase + row) * D + lane * 4]);
            __half2 p0 = __halves2half2(__float2half(v.x), __float2half(v.y));
            __half2 p1 = __halves2half2(__float2half(v.z), __float2half(v.w));
            uint32_t off = (uint32_t)(row * 256 + ((chunk ^ (row & 7)) * 16) + half * 8);
            *(uint2*)(smem + SM_A + off) = make_uint2(*(uint32_t*)&p0, *(uint32_t*)&p1);
        }
    }
    __syncthreads();

    // ---- MMA: warp (wm, wn): rows wm*32..+31, n8 blocks wn*4..+3 ----
    int wm = wid >> 2, wn = wid & 3;
    float c[2][4][4];
#pragma unroll
    for (int m = 0; m < 2; ++m)
#pragma unroll
        for (int n = 0; n < 4; ++n)
#pragma unroll
            for (int j = 0; j < 4; ++j) c[m][n][j] = 0.f;

    int ar = (lane & 7) + ((lane >> 3) & 1) * 8;   // row within m16
    int aco = lane >> 4;                           // k16-half chunk
    int axr = lane & 7;
    uint32_t aBase = sb + SM_A + (uint32_t)((wm * 32 + ar) * 256);

#pragma unroll
    for (int kb = 0; kb < 8; ++kb) {
        uint32_t au = (uint32_t)((2 * kb + aco) ^ axr) * 16;
        uint32_t Af[2][4];
        LDSM4(Af[0][0], Af[0][1], Af[0][2], Af[0][3], aBase + au);
        LDSM4(Af[1][0], Af[1][1], Af[1][2], Af[1][3], aBase + 16 * 256 + au);

        uint2 B[4];
#pragma unroll
        for (int n = 0; n < 4; ++n) B[n] = g_Bfrag[kb][wn * 4 + n][lane];
#pragma unroll
        for (int m = 0; m < 2; ++m)
#pragma unroll
            for (int n = 0; n < 4; ++n)
                MMA16816(c[m][n], Af[m][0], Af[m][1], Af[m][2], Af[m][3], B[n].x, B[n].y);
    }

    __syncthreads();   // all A reads done before Ds aliases the region

    // stage C -> Ds[128][132]
    float* Ds = (float*)(smem + SM_A);
    {
        int rq = lane >> 2, cq = (lane & 3) * 2;
#pragma unroll
        for (int m = 0; m < 2; ++m) {
            int r0 = wm * 32 + m * 16 + rq;
#pragma unroll
            for (int n = 0; n < 4; ++n) {
                int cc = (wn * 4 + n) * 8 + cq;
                *(float2*)&Ds[r0 * DS_PITCH + cc] = make_float2(c[m][n][0], c[m][n][1]);
                *(float2*)&Ds[(r0 + 8) * DS_PITCH + cc] = make_float2(c[m][n][2], c[m][n][3]);
            }
        }
    }
    __syncthreads();

    // ---- epilogue: coalescing-exact mapping ----
    // thread (ty 0..31, tx 0..15): rows er = ty*4+i, cols {tx*4..+3} and {64+tx*4..+3}.
    // head of chunk1 = tx>>2, head of chunk2 = 4+(tx>>2); 4-lane shfl groups per head.
    const float isd = 0.25f;
    int ty = tid >> 4, tx = tid & 15;
    int ca = tx << 2;          // chunk1 col
    int cb = 64 + ca;          // chunk2 col
    const int* s_src = (const int*)(smem + SM_SRC);
    const int* s_dst = (const int*)(smem + SM_DST);

#pragma unroll
    for (int i = 0; i < 4; ++i) {
        int er = ty * 4 + i;
        int e = rowBase + er;
        int sn = s_src[er], dn = s_dst[er];

        float4 ka = *(const float4*)&g_K[sn * D + ca];
        float4 kb4 = *(const float4*)&g_K[sn * D + cb];
        float4 qa = *(const float4*)&g_Q[dn * D + ca];
        float4 qb = *(const float4*)&g_Q[dn * D + cb];

        float4 pa = *(const float4*)&Ds[er * DS_PITCH + ca];
        float4 pb = *(const float4*)&Ds[er * DS_PITCH + cb];

        float sa[4], sbv[4];
        float parta, partb;
        {
            float kq0 = fminf(fmaxf(ka.x * qa.x * isd, -5.f), 5.f);
            float kq1 = fminf(fmaxf(ka.y * qa.y * isd, -5.f), 5.f);
            float kq2 = fminf(fmaxf(ka.z * qa.z * isd, -5.f), 5.f);
            float kq3 = fminf(fmaxf(ka.w * qa.w * isd, -5.f), 5.f);
            sa[0] = kq0 * pa.x; sa[1] = kq1 * pa.y; sa[2] = kq2 * pa.z; sa[3] = kq3 * pa.w;
            parta = sa[0] + sa[1] + sa[2] + sa[3];
        }
        {
            float kq0 = fminf(fmaxf(kb4.x * qb.x * isd, -5.f), 5.f);
            float kq1 = fminf(fmaxf(kb4.y * qb.y * isd, -5.f), 5.f);
            float kq2 = fminf(fmaxf(kb4.z * qb.z * isd, -5.f), 5.f);
            float kq3 = fminf(fmaxf(kb4.w * qb.w * isd, -5.f), 5.f);
            sbv[0] = kq0 * pb.x; sbv[1] = kq1 * pb.y; sbv[2] = kq2 * pb.z; sbv[3] = kq3 * pb.w;
            partb = sbv[0] + sbv[1] + sbv[2] + sbv[3];
        }

        __stcs((float4*)&e_out[(size_t)e * D + ca], make_float4(sa[0], sa[1], sa[2], sa[3]));
        __stcs((float4*)&e_out[(size_t)e * D + cb], make_float4(sbv[0], sbv[1], sbv[2], sbv[3]));

        // head sums over 4-lane groups
        parta += __shfl_xor_sync(0xffffffffu, parta, 1);
        parta += __shfl_xor_sync(0xffffffffu, parta, 2);
        partb += __shfl_xor_sync(0xffffffffu, partb, 1);
        partb += __shfl_xor_sync(0xffffffffu, partb, 2);
        float s1 = __expf(fminf(fmaxf(parta, -5.f), 5.f));
        float s2 = __expf(fminf(fmaxf(partb, -5.f), 5.f));

        float4 va = *(const float4*)&g_V[sn * D + ca];
        float4 vb = *(const float4*)&g_V[sn * D + cb];
        float* w = &g_wV[dn * D + ca];
        asm volatile("red.global.add.v4.f32 [%0], {%1,%2,%3,%4};"
                     :: "l"(w), "f"(va.x * s1), "f"(va.y * s1), "f"(va.z * s1), "f"(va.w * s1)
                     : "memory");
        asm volatile("red.global.add.v4.f32 [%0], {%1,%2,%3,%4};"
                     :: "l"(w + 64), "f"(vb.x * s2), "f"(vb.y * s2), "f"(vb.z * s2), "f"(vb.w * s2)
                     : "memory");
        if ((tx & 3) == 0) {
            atomicAdd(&g_z[dn * H + (tx >> 2)], s1);
            atomicAdd(&g_z[dn * H + 4 + (tx >> 2)], s2);
        }
    }
}

// ---------------- normalize ----------------
__global__ void norm_kernel(float* __restrict__ h_out) {
    int i = blockIdx.x * blockDim.x + threadIdx.x;
    if (i < NN * D) {
        int n = i >> 7;
        int hh = (i & 127) >> 4;
        h_out[i] = g_wV[i] / (g_z[n * H + hh] + 1e-6f);
    }
}

// ---------------- launch ----------------
extern "C" void kernel_launch(void* const* d_in, const int* in_sizes, int n_in,
                              void* d_out, int out_size) {
    const float* node_feats = (const float*)d_in[0];
    const float* edge_feats = (const float*)d_in[1];
    const int* src = (const int*)d_in[2];
    const int* dst = (const int*)d_in[3];
    const float* WQ = (const float*)d_in[4];
    const float* WK = (const float*)d_in[5];
    const float* WV = (const float*)d_in[6];
    const float* We = (const float*)d_in[7];

    float* out = (float*)d_out;
    float* h_out = out;                  // [NN, H, DH]
    float* e_out = out + (size_t)NN * D; // [NE, H, DH]

    static int smem_set = 0;
    if (!smem_set) {
        cudaFuncSetAttribute(edge_mma_kernel, cudaFuncAttributeMaxDynamicSharedMemorySize, SM_EDGE_TOTAL);
        smem_set = 1;
    }

    zero_kernel<<<(NN * D + 255) / 256, 256>>>();
    prep_Bfrag_kernel<<<16, 256>>>(We);

    dim3 gn((NN + 127) / 128, 3);
    node_proj_kernel<<<gn, 256>>>(node_feats, WQ, WK, WV);

    edge_mma_kernel<<<NE / TILE, 512, SM_EDGE_TOTAL>>>(edge_feats, src, dst, e_out);

    norm_kernel<<<(NN * D + 255) / 256, 256>>>(h_out);
}

// round 7
// speedup vs baseline: 2.8742x; 1.2065x over previous
#include <cuda_runtime.h>
#include <cuda_fp16.h>
#include <cuda_bf16.h>
#include <cstdint>

#define NN 10000
#define NE 640000
#define D 128
#define H 8

// ---------------- scratch (no allocations allowed) ----------------
__device__ float g_Q[NN * D];
__device__ float g_K[NN * D];
__device__ float g_V[NN * D];
__device__ float g_wV[NN * D];
__device__ float g_z[NN * H];
// We fp16 B-fragments, n8 pairs packed: [kb(8)][p(8)][lane(32)] -> {b0(2p),b1(2p),b0(2p+1),b1(2p+1)}
__device__ uint4 g_BfragE[8][8][32];
// WQ/WK/WV bf16 hi/lo B-fragments: [w(3)][img(2)][kb(8)][n8(16)][lane(32)] -> {b0,b1}
__device__ uint2 g_BfragN[3][2][8][16][32];

__device__ __forceinline__ uint32_t smem_u32(const void* p) {
    uint32_t a;
    asm("{ .reg .u64 t; cvta.to.shared.u64 t, %1; cvt.u32.u64 %0, t; }" : "=r"(a) : "l"(p));
    return a;
}

#define LDSM4(r0, r1, r2, r3, a) \
    asm volatile("ldmatrix.sync.aligned.m8n8.x4.shared.b16 {%0,%1,%2,%3}, [%4];" \
        : "=r"(r0), "=r"(r1), "=r"(r2), "=r"(r3) : "r"(a))

#define MMA16816F(c, a0, a1, a2, a3, b0, b1) \
    asm volatile("mma.sync.aligned.m16n8k16.row.col.f32.f16.f16.f32 " \
        "{%0,%1,%2,%3}, {%4,%5,%6,%7}, {%8,%9}, {%0,%1,%2,%3};" \
        : "+f"((c)[0]), "+f"((c)[1]), "+f"((c)[2]), "+f"((c)[3]) \
        : "r"(a0), "r"(a1), "r"(a2), "r"(a3), "r"(b0), "r"(b1))

#define MMA16816B(c, a0, a1, a2, a3, b0, b1) \
    asm volatile("mma.sync.aligned.m16n8k16.row.col.f32.bf16.bf16.f32 " \
        "{%0,%1,%2,%3}, {%4,%5,%6,%7}, {%8,%9}, {%0,%1,%2,%3};" \
        : "+f"((c)[0]), "+f"((c)[1]), "+f"((c)[2]), "+f"((c)[3]) \
        : "r"(a0), "r"(a1), "r"(a2), "r"(a3), "r"(b0), "r"(b1))

// ---------------- setup: zero accumulators + all weight fragments ----------------
__global__ void setup_kernel(const float* __restrict__ WQ, const float* __restrict__ WK,
                             const float* __restrict__ WV, const float* __restrict__ We) {
    int i = blockIdx.x * blockDim.x + threadIdx.x;
    if (i < NN * D) g_wV[i] = 0.f;
    if (i < NN * H) g_z[i] = 0.f;

    if (i < 2048) {
        // We fp16 fragments (uint4-paired)
        int kb = i >> 8, p = (i >> 5) & 7, lane = i & 31;
        int k0 = kb * 16 + 2 * (lane & 3);
        int rsel = lane >> 2;
        uint32_t v[4];
#pragma unroll
        for (int half = 0; half < 2; ++half) {
            int n = (2 * p + half) * 8 + rsel;
            __half2 p0 = __halves2half2(__float2half(We[k0 * 128 + n]),
                                        __float2half(We[(k0 + 1) * 128 + n]));
            __half2 p1 = __halves2half2(__float2half(We[(k0 + 8) * 128 + n]),
                                        __float2half(We[(k0 + 9) * 128 + n]));
            v[half * 2 + 0] = *(uint32_t*)&p0;
            v[half * 2 + 1] = *(uint32_t*)&p1;
        }
        g_BfragE[kb][p][lane] = make_uint4(v[0], v[1], v[2], v[3]);
    } else if (i < 2048 + 24576) {
        int j = i - 2048;
        int w = j >> 13;                // 0..2
        int r = j & 8191;
        int img = r >> 12;
        int rr = r & 4095;
        int kb = rr >> 9, n8 = (rr >> 5) & 15, lane = rr & 31;
        const float* W = (w == 0) ? WQ : (w == 1) ? WK : WV;
        int n = n8 * 8 + (lane >> 2);
        int k0 = kb * 16 + 2 * (lane & 3);
        float f[4] = { W[k0 * 128 + n], W[(k0 + 1) * 128 + n],
                       W[(k0 + 8) * 128 + n], W[(k0 + 9) * 128 + n] };
        __nv_bfloat16 v[4];
#pragma unroll
        for (int t = 0; t < 4; ++t) {
            __nv_bfloat16 h = __float2bfloat16(f[t]);
            v[t] = (img == 0) ? h : __float2bfloat16(f[t] - __bfloat162float(h));
        }
        __nv_bfloat162 p0(v[0], v[1]), p1(v[2], v[3]);
        g_BfragN[w][img][kb][n8][lane] = make_uint2(*(uint32_t*)&p0, *(uint32_t*)&p1);
    }
}

// ---------------- node projection via bf16 3-pass mma ----------------
// grid (79, 3); 512 threads; TILE 128 rows.
// smem: A_hi(32KB)@0, A_lo(32KB)@32768; Ds[128][136] f32 aliases after MMA.
#define DS_PITCH 136
#define SM_NODE_TOTAL (128 * DS_PITCH * 4)   // 69632

__global__ __launch_bounds__(512, 2)
void node_mma_kernel(const float* __restrict__ X) {
    extern __shared__ char smem[];
    uint32_t sb = smem_u32(smem);
    int tid = threadIdx.x, wid = tid >> 5, lane = tid & 31;
    int w = blockIdx.y;
    float* Out = (w == 0) ? g_Q : (w == 1) ? g_K : g_V;
    int rowBase = blockIdx.x << 7;

    // convert X tile -> bf16 hi/lo swizzled images
    {
        int row0 = wid * 8;
        int chunk = lane >> 1, half = lane & 1;
#pragma unroll
        for (int j = 0; j < 8; ++j) {
            int row = row0 + j;
            int gr = rowBase + row; if (gr >= NN) gr = NN - 1;
            float4 v = *(const float4*)&X[(size_t)gr * D + lane * 4];
            __nv_bfloat16 h0 = __float2bfloat16(v.x), h1 = __float2bfloat16(v.y);
            __nv_bfloat16 h2 = __float2bfloat16(v.z), h3 = __float2bfloat16(v.w);
            __nv_bfloat16 l0 = __float2bfloat16(v.x - __bfloat162float(h0));
            __nv_bfloat16 l1 = __float2bfloat16(v.y - __bfloat162float(h1));
            __nv_bfloat16 l2 = __float2bfloat16(v.z - __bfloat162float(h2));
            __nv_bfloat16 l3 = __float2bfloat16(v.w - __bfloat162float(h3));
            __nv_bfloat162 hp0(h0, h1), hp1(h2, h3), lp0(l0, l1), lp1(l2, l3);
            uint32_t off = (uint32_t)(row * 256 + ((chunk ^ (row & 7)) * 16) + half * 8);
            *(uint2*)(smem + off) = make_uint2(*(uint32_t*)&hp0, *(uint32_t*)&hp1);
            *(uint2*)(smem + 32768 + off) = make_uint2(*(uint32_t*)&lp0, *(uint32_t*)&lp1);
        }
    }
    __syncthreads();

    int wm = wid >> 2, wn = wid & 3;
    float c[2][4][4];
#pragma unroll
    for (int m = 0; m < 2; ++m)
#pragma unroll
        for (int n = 0; n < 4; ++n)
#pragma unroll
            for (int j = 0; j < 4; ++j) c[m][n][j] = 0.f;

    int ar = (lane & 7) + ((lane >> 3) & 1) * 8;
    int aco = lane >> 4;
    int axr = lane & 7;
    uint32_t aBase = sb + (uint32_t)((wm * 32 + ar) * 256);

#pragma unroll
    for (int kb = 0; kb < 8; ++kb) {
        uint32_t au = (uint32_t)((2 * kb + aco) ^ axr) * 16;
        uint32_t Af[2][4];
        LDSM4(Af[0][0], Af[0][1], Af[0][2], Af[0][3], aBase + au);
        LDSM4(Af[1][0], Af[1][1], Af[1][2], Af[1][3], aBase + 16 * 256 + au);

        uint2 Bh[4], Bl[4];
#pragma unroll
        for (int n = 0; n < 4; ++n) Bh[n] = g_BfragN[w][0][kb][wn * 4 + n][lane];
#pragma unroll
        for (int m = 0; m < 2; ++m)
#pragma unroll
            for (int n = 0; n < 4; ++n)
                MMA16816B(c[m][n], Af[m][0], Af[m][1], Af[m][2], Af[m][3], Bh[n].x, Bh[n].y);
#pragma unroll
        for (int n = 0; n < 4; ++n) Bl[n] = g_BfragN[w][1][kb][wn * 4 + n][lane];
#pragma unroll
        for (int m = 0; m < 2; ++m)
#pragma unroll
            for (int n = 0; n < 4; ++n)
                MMA16816B(c[m][n], Af[m][0], Af[m][1], Af[m][2], Af[m][3], Bl[n].x, Bl[n].y);

        LDSM4(Af[0][0], Af[0][1], Af[0][2], Af[0][3], aBase + 32768 + au);
        LDSM4(Af[1][0], Af[1][1], Af[1][2], Af[1][3], aBase + 32768 + 16 * 256 + au);
#pragma unroll
        for (int m = 0; m < 2; ++m)
#pragma unroll
            for (int n = 0; n < 4; ++n)
                MMA16816B(c[m][n], Af[m][0], Af[m][1], Af[m][2], Af[m][3], Bh[n].x, Bh[n].y);
    }
    __syncthreads();

    float* Ds = (float*)smem;
    {
        int rq = lane >> 2, cq = (lane & 3) * 2;
#pragma unroll
        for (int m = 0; m < 2; ++m) {
            int r0 = wm * 32 + m * 16 + rq;
#pragma unroll
            for (int n = 0; n < 4; ++n) {
                int cc = (wn * 4 + n) * 8 + cq;
                *(float2*)&Ds[r0 * DS_PITCH + cc] = make_float2(c[m][n][0], c[m][n][1]);
                *(float2*)&Ds[(r0 + 8) * DS_PITCH + cc] = make_float2(c[m][n][2], c[m][n][3]);
            }
        }
    }
    __syncthreads();

    int ty = tid >> 4, tx = tid & 15;
#pragma unroll
    for (int i = 0; i < 4; ++i) {
        int er = ty * 4 + i;
        int gr = rowBase + er;
        if (gr < NN) {
            *(float4*)&Out[(size_t)gr * D + tx * 4] = *(const float4*)&Ds[er * DS_PITCH + tx * 4];
            *(float4*)&Out[(size_t)gr * D + 64 + tx * 4] = *(const float4*)&Ds[er * DS_PITCH + 64 + tx * 4];
        }
    }
}

// ---------------- fused edge kernel v5 ----------------
// TILE=128 edges, 16 warps 4m x 4n. A fp16 in smem; B uint4-paired fragments from L1/L2.
// smem: [0] src[128], [512] dst[128], [1024] A(32KB); Ds[128][136] f32 aliases A after MMA.
#define SM_SRC  0
#define SM_DST  512
#define SM_A    1024
#define SM_EDGE_TOTAL (1024 + 128 * DS_PITCH * 4)   // 70656
#define TILE 128

__global__ __launch_bounds__(512, 2)
void edge_mma_kernel(const float* __restrict__ Ef,
                     const int* __restrict__ src, const int* __restrict__ dst,
                     float* __restrict__ e_out) {
    extern __shared__ char smem[];
    uint32_t sb = smem_u32(smem);
    int tid = threadIdx.x, wid = tid >> 5, lane = tid & 31;
    int rowBase = blockIdx.x << 7;

    if (tid < 128) {
        ((int*)(smem + SM_SRC))[tid] = src[rowBase + tid];
        ((int*)(smem + SM_DST))[tid] = dst[rowBase + tid];
    }

    // convert Ef tile (128x128 f32) -> fp16 swizzled image
    {
        int row0 = wid * 8;
        int chunk = lane >> 1, half = lane & 1;
#pragma unroll
        for (int j = 0; j < 8; ++j) {
            int row = row0 + j;
            float4 v = __ldcs((const float4*)&Ef[(size_t)(rowBase + row) * D + lane * 4]);
            __half2 p0 = __halves2half2(__float2half(v.x), __float2half(v.y));
            __half2 p1 = __halves2half2(__float2half(v.z), __float2half(v.w));
            uint32_t off = (uint32_t)(row * 256 + ((chunk ^ (row & 7)) * 16) + half * 8);
            *(uint2*)(smem + SM_A + off) = make_uint2(*(uint32_t*)&p0, *(uint32_t*)&p1);
        }
    }
    __syncthreads();

    int wm = wid >> 2, wn = wid & 3;
    float c[2][4][4];
#pragma unroll
    for (int m = 0; m < 2; ++m)
#pragma unroll
        for (int n = 0; n < 4; ++n)
#pragma unroll
            for (int j = 0; j < 4; ++j) c[m][n][j] = 0.f;

    int ar = (lane & 7) + ((lane >> 3) & 1) * 8;
    int aco = lane >> 4;
    int axr = lane & 7;
    uint32_t aBase = sb + SM_A + (uint32_t)((wm * 32 + ar) * 256);

#pragma unroll
    for (int kb = 0; kb < 8; ++kb) {
        uint32_t au = (uint32_t)((2 * kb + aco) ^ axr) * 16;
        uint32_t Af[2][4];
        LDSM4(Af[0][0], Af[0][1], Af[0][2], Af[0][3], aBase + au);
        LDSM4(Af[1][0], Af[1][1], Af[1][2], Af[1][3], aBase + 16 * 256 + au);

        uint4 Bq0 = g_BfragE[kb][wn * 2 + 0][lane];
        uint4 Bq1 = g_BfragE[kb][wn * 2 + 1][lane];
#pragma unroll
        for (int m = 0; m < 2; ++m) {
            MMA16816F(c[m][0], Af[m][0], Af[m][1], Af[m][2], Af[m][3], Bq0.x, Bq0.y);
            MMA16816F(c[m][1], Af[m][0], Af[m][1], Af[m][2], Af[m][3], Bq0.z, Bq0.w);
            MMA16816F(c[m][2], Af[m][0], Af[m][1], Af[m][2], Af[m][3], Bq1.x, Bq1.y);
            MMA16816F(c[m][3], Af[m][0], Af[m][1], Af[m][2], Af[m][3], Bq1.z, Bq1.w);
        }
    }
    __syncthreads();

    float* Ds = (float*)(smem + SM_A);
    {
        int rq = lane >> 2, cq = (lane & 3) * 2;
#pragma unroll
        for (int m = 0; m < 2; ++m) {
            int r0 = wm * 32 + m * 16 + rq;
#pragma unroll
            for (int n = 0; n < 4; ++n) {
                int cc = (wn * 4 + n) * 8 + cq;
                *(float2*)&Ds[r0 * DS_PITCH + cc] = make_float2(c[m][n][0], c[m][n][1]);
                *(float2*)&Ds[(r0 + 8) * DS_PITCH + cc] = make_float2(c[m][n][2], c[m][n][3]);
            }
        }
    }
    __syncthreads();

    // ---- epilogue: coalescing-exact mapping ----
    const float isd = 0.25f;
    int ty = tid >> 4, tx = tid & 15;
    int ca = tx << 2;
    int cb = 64 + ca;
    const int* s_src = (const int*)(smem + SM_SRC);
    const int* s_dst = (const int*)(smem + SM_DST);

#pragma unroll
    for (int i = 0; i < 4; ++i) {
        int er = ty * 4 + i;
        int e = rowBase + er;
        int sn = s_src[er], dn = s_dst[er];

        float4 ka = *(const float4*)&g_K[sn * D + ca];
        float4 kb4 = *(const float4*)&g_K[sn * D + cb];
        float4 qa = *(const float4*)&g_Q[dn * D + ca];
        float4 qb = *(const float4*)&g_Q[dn * D + cb];

        float4 pa = *(const float4*)&Ds[er * DS_PITCH + ca];
        float4 pb = *(const float4*)&Ds[er * DS_PITCH + cb];

        float sa[4], sbv[4];
        float parta, partb;
        {
            float kq0 = fminf(fmaxf(ka.x * qa.x * isd, -5.f), 5.f);
            float kq1 = fminf(fmaxf(ka.y * qa.y * isd, -5.f), 5.f);
            float kq2 = fminf(fmaxf(ka.z * qa.z * isd, -5.f), 5.f);
            float kq3 = fminf(fmaxf(ka.w * qa.w * isd, -5.f), 5.f);
            sa[0] = kq0 * pa.x; sa[1] = kq1 * pa.y; sa[2] = kq2 * pa.z; sa[3] = kq3 * pa.w;
            parta = sa[0] + sa[1] + sa[2] + sa[3];
        }
        {
            float kq0 = fminf(fmaxf(kb4.x * qb.x * isd, -5.f), 5.f);
            float kq1 = fminf(fmaxf(kb4.y * qb.y * isd, -5.f), 5.f);
            float kq2 = fminf(fmaxf(kb4.z * qb.z * isd, -5.f), 5.f);
            float kq3 = fminf(fmaxf(kb4.w * qb.w * isd, -5.f), 5.f);
            sbv[0] = kq0 * pb.x; sbv[1] = kq1 * pb.y; sbv[2] = kq2 * pb.z; sbv[3] = kq3 * pb.w;
            partb = sbv[0] + sbv[1] + sbv[2] + sbv[3];
        }

        __stcs((float4*)&e_out[(size_t)e * D + ca], make_float4(sa[0], sa[1], sa[2], sa[3]));
        __stcs((float4*)&e_out[(size_t)e * D + cb], make_float4(sbv[0], sbv[1], sbv[2], sbv[3]));

        parta += __shfl_xor_sync(0xffffffffu, parta, 1);
        parta += __shfl_xor_sync(0xffffffffu, parta, 2);
        partb += __shfl_xor_sync(0xffffffffu, partb, 1);
        partb += __shfl_xor_sync(0xffffffffu, partb, 2);
        float s1 = __expf(fminf(fmaxf(parta, -5.f), 5.f));
        float s2 = __expf(fminf(fmaxf(partb, -5.f), 5.f));

        float4 va = *(const float4*)&g_V[sn * D + ca];
        float4 vb = *(const float4*)&g_V[sn * D + cb];
        float* w = &g_wV[dn * D + ca];
        asm volatile("red.global.add.v4.f32 [%0], {%1,%2,%3,%4};"
                     :: "l"(w), "f"(va.x * s1), "f"(va.y * s1), "f"(va.z * s1), "f"(va.w * s1)
                     : "memory");
        asm volatile("red.global.add.v4.f32 [%0], {%1,%2,%3,%4};"
                     :: "l"(w + 64), "f"(vb.x * s2), "f"(vb.y * s2), "f"(vb.z * s2), "f"(vb.w * s2)
                     : "memory");
        if ((tx & 3) == 0) {
            atomicAdd(&g_z[dn * H + (tx >> 2)], s1);
            atomicAdd(&g_z[dn * H + 4 + (tx >> 2)], s2);
        }
    }
}

// ---------------- normalize ----------------
__global__ void norm_kernel(float* __restrict__ h_out) {
    int i = blockIdx.x * blockDim.x + threadIdx.x;
    if (i < NN * D) {
        int n = i >> 7;
        int hh = (i & 127) >> 4;
        h_out[i] = g_wV[i] / (g_z[n * H + hh] + 1e-6f);
    }
}

// ---------------- launch ----------------
extern "C" void kernel_launch(void* const* d_in, const int* in_sizes, int n_in,
                              void* d_out, int out_size) {
    const float* node_feats = (const float*)d_in[0];
    const float* edge_feats = (const float*)d_in[1];
    const int* src = (const int*)d_in[2];
    const int* dst = (const int*)d_in[3];
    const float* WQ = (const float*)d_in[4];
    const float* WK = (const float*)d_in[5];
    const float* WV = (const float*)d_in[6];
    const float* We = (const float*)d_in[7];

    float* out = (float*)d_out;
    float* h_out = out;                  // [NN, H, DH]
    float* e_out = out + (size_t)NN * D; // [NE, H, DH]

    static int smem_set = 0;
    if (!smem_set) {
        cudaFuncSetAttribute(edge_mma_kernel, cudaFuncAttributeMaxDynamicSharedMemorySize, SM_EDGE_TOTAL);
        cudaFuncSetAttribute(node_mma_kernel, cudaFuncAttributeMaxDynamicSharedMemorySize, SM_NODE_TOTAL);
        smem_set = 1;
    }

    setup_kernel<<<(NN * D + 255) / 256, 256>>>(WQ, WK, WV, We);

    dim3 gn((NN + 127) / 128, 3);
    node_mma_kernel<<<gn, 512, SM_NODE_TOTAL>>>(node_feats);

    edge_mma_kernel<<<NE / TILE, 512, SM_EDGE_TOTAL>>>(edge_feats, src, dst, e_out);

    norm_kernel<<<(NN * D + 255) / 256, 256>>>(h_out);
}

// round 8
// speedup vs baseline: 3.1667x; 1.1017x over previous
#include <cuda_runtime.h>
#include <cuda_fp16.h>
#include <cuda_bf16.h>
#include <cstdint>

#define NN 10000
#define NE 640000
#define D 128
#define H 8

// ---------------- scratch (no allocations allowed) ----------------
__device__ __half g_Qh[NN * D];
__device__ __half g_Kh[NN * D];
__device__ __half g_Vh[NN * D];
__device__ float g_wV[NN * D];
__device__ float g_z[NN * H];
// We fp16 B-fragments, n8 pairs packed: [kb(8)][p(8)][lane(32)] -> {b0,b1,b0',b1'}
__device__ uint4 g_BfragE[8][8][32];
// WQ/WK/WV bf16 hi/lo B-fragments: [w(3)][img(2)][kb(8)][n8(16)][lane(32)] -> {b0,b1}
__device__ uint2 g_BfragN[3][2][8][16][32];

__device__ __forceinline__ uint32_t smem_u32(const void* p) {
    uint32_t a;
    asm("{ .reg .u64 t; cvta.to.shared.u64 t, %1; cvt.u32.u64 %0, t; }" : "=r"(a) : "l"(p));
    return a;
}

#define LDSM4(r0, r1, r2, r3, a) \
    asm volatile("ldmatrix.sync.aligned.m8n8.x4.shared.b16 {%0,%1,%2,%3}, [%4];" \
        : "=r"(r0), "=r"(r1), "=r"(r2), "=r"(r3) : "r"(a))

#define MMA16816F(c, a0, a1, a2, a3, b0, b1) \
    asm volatile("mma.sync.aligned.m16n8k16.row.col.f32.f16.f16.f32 " \
        "{%0,%1,%2,%3}, {%4,%5,%6,%7}, {%8,%9}, {%0,%1,%2,%3};" \
        : "+f"((c)[0]), "+f"((c)[1]), "+f"((c)[2]), "+f"((c)[3]) \
        : "r"(a0), "r"(a1), "r"(a2), "r"(a3), "r"(b0), "r"(b1))

#define MMA16816B(c, a0, a1, a2, a3, b0, b1) \
    asm volatile("mma.sync.aligned.m16n8k16.row.col.f32.bf16.bf16.f32 " \
        "{%0,%1,%2,%3}, {%4,%5,%6,%7}, {%8,%9}, {%0,%1,%2,%3};" \
        : "+f"((c)[0]), "+f"((c)[1]), "+f"((c)[2]), "+f"((c)[3]) \
        : "r"(a0), "r"(a1), "r"(a2), "r"(a3), "r"(b0), "r"(b1))

// ---------------- setup: zero accumulators + all weight fragments ----------------
__global__ __launch_bounds__(512)
void setup_kernel(const float* __restrict__ WQ, const float* __restrict__ WK,
                  const float* __restrict__ WV, const float* __restrict__ We) {
    int i = blockIdx.x * blockDim.x + threadIdx.x;
    if (i < NN * D / 4) ((float4*)g_wV)[i] = make_float4(0.f, 0.f, 0.f, 0.f);
    if (i < NN * H) g_z[i] = 0.f;

    if (i < 2048) {
        int kb = i >> 8, p = (i >> 5) & 7, lane = i & 31;
        int k0 = kb * 16 + 2 * (lane & 3);
        int rsel = lane >> 2;
        uint32_t v[4];
#pragma unroll
        for (int half = 0; half < 2; ++half) {
            int n = (2 * p + half) * 8 + rsel;
            __half2 p0 = __halves2half2(__float2half(We[k0 * 128 + n]),
                                        __float2half(We[(k0 + 1) * 128 + n]));
            __half2 p1 = __halves2half2(__float2half(We[(k0 + 8) * 128 + n]),
                                        __float2half(We[(k0 + 9) * 128 + n]));
            v[half * 2 + 0] = *(uint32_t*)&p0;
            v[half * 2 + 1] = *(uint32_t*)&p1;
        }
        g_BfragE[kb][p][lane] = make_uint4(v[0], v[1], v[2], v[3]);
    } else if (i < 2048 + 24576) {
        int j = i - 2048;
        int w = j >> 13;
        int r = j & 8191;
        int img = r >> 12;
        int rr = r & 4095;
        int kb = rr >> 9, n8 = (rr >> 5) & 15, lane = rr & 31;
        const float* W = (w == 0) ? WQ : (w == 1) ? WK : WV;
        int n = n8 * 8 + (lane >> 2);
        int k0 = kb * 16 + 2 * (lane & 3);
        float f[4] = { W[k0 * 128 + n], W[(k0 + 1) * 128 + n],
                       W[(k0 + 8) * 128 + n], W[(k0 + 9) * 128 + n] };
        __nv_bfloat16 v[4];
#pragma unroll
        for (int t = 0; t < 4; ++t) {
            __nv_bfloat16 h = __float2bfloat16(f[t]);
            v[t] = (img == 0) ? h : __float2bfloat16(f[t] - __bfloat162float(h));
        }
        __nv_bfloat162 p0(v[0], v[1]), p1(v[2], v[3]);
        g_BfragN[w][img][kb][n8][lane] = make_uint2(*(uint32_t*)&p0, *(uint32_t*)&p1);
    }
}

// ---------------- node projection via bf16 3-pass mma, fp16 output ----------------
#define DS_PITCH 136
#define SM_NODE_TOTAL (128 * DS_PITCH * 4)   // 69632

__global__ __launch_bounds__(512, 2)
void node_mma_kernel(const float* __restrict__ X) {
    extern __shared__ char smem[];
    uint32_t sb = smem_u32(smem);
    int tid = threadIdx.x, wid = tid >> 5, lane = tid & 31;
    int w = blockIdx.y;
    __half* Out = (w == 0) ? g_Qh : (w == 1) ? g_Kh : g_Vh;
    int rowBase = blockIdx.x << 7;

    // convert X tile -> bf16 hi/lo swizzled images
    {
        int row0 = wid * 8;
        int chunk = lane >> 1, half = lane & 1;
#pragma unroll
        for (int j = 0; j < 8; ++j) {
            int row = row0 + j;
            int gr = rowBase + row; if (gr >= NN) gr = NN - 1;
            float4 v = *(const float4*)&X[(size_t)gr * D + lane * 4];
            __nv_bfloat16 h0 = __float2bfloat16(v.x), h1 = __float2bfloat16(v.y);
            __nv_bfloat16 h2 = __float2bfloat16(v.z), h3 = __float2bfloat16(v.w);
            __nv_bfloat16 l0 = __float2bfloat16(v.x - __bfloat162float(h0));
            __nv_bfloat16 l1 = __float2bfloat16(v.y - __bfloat162float(h1));
            __nv_bfloat16 l2 = __float2bfloat16(v.z - __bfloat162float(h2));
            __nv_bfloat16 l3 = __float2bfloat16(v.w - __bfloat162float(h3));
            __nv_bfloat162 hp0(h0, h1), hp1(h2, h3), lp0(l0, l1), lp1(l2, l3);
            uint32_t off = (uint32_t)(row * 256 + ((chunk ^ (row & 7)) * 16) + half * 8);
            *(uint2*)(smem + off) = make_uint2(*(uint32_t*)&hp0, *(uint32_t*)&hp1);
            *(uint2*)(smem + 32768 + off) = make_uint2(*(uint32_t*)&lp0, *(uint32_t*)&lp1);
        }
    }
    __syncthreads();

    int wm = wid >> 2, wn = wid & 3;
    float c[2][4][4];
#pragma unroll
    for (int m = 0; m < 2; ++m)
#pragma unroll
        for (int n = 0; n < 4; ++n)
#pragma unroll
            for (int j = 0; j < 4; ++j) c[m][n][j] = 0.f;

    int ar = (lane & 7) + ((lane >> 3) & 1) * 8;
    int aco = lane >> 4;
    int axr = lane & 7;
    uint32_t aBase = sb + (uint32_t)((wm * 32 + ar) * 256);

#pragma unroll
    for (int kb = 0; kb < 8; ++kb) {
        uint32_t au = (uint32_t)((2 * kb + aco) ^ axr) * 16;
        uint32_t Af[2][4];
        LDSM4(Af[0][0], Af[0][1], Af[0][2], Af[0][3], aBase + au);
        LDSM4(Af[1][0], Af[1][1], Af[1][2], Af[1][3], aBase + 16 * 256 + au);

        uint2 Bh[4], Bl[4];
#pragma unroll
        for (int n = 0; n < 4; ++n) Bh[n] = g_BfragN[w][0][kb][wn * 4 + n][lane];
#pragma unroll
        for (int m = 0; m < 2; ++m)
#pragma unroll
            for (int n = 0; n < 4; ++n)
                MMA16816B(c[m][n], Af[m][0], Af[m][1], Af[m][2], Af[m][3], Bh[n].x, Bh[n].y);
#pragma unroll
        for (int n = 0; n < 4; ++n) Bl[n] = g_BfragN[w][1][kb][wn * 4 + n][lane];
#pragma unroll
        for (int m = 0; m < 2; ++m)
#pragma unroll
            for (int n = 0; n < 4; ++n)
                MMA16816B(c[m][n], Af[m][0], Af[m][1], Af[m][2], Af[m][3], Bl[n].x, Bl[n].y);

        LDSM4(Af[0][0], Af[0][1], Af[0][2], Af[0][3], aBase + 32768 + au);
        LDSM4(Af[1][0], Af[1][1], Af[1][2], Af[1][3], aBase + 32768 + 16 * 256 + au);
#pragma unroll
        for (int m = 0; m < 2; ++m)
#pragma unroll
            for (int n = 0; n < 4; ++n)
                MMA16816B(c[m][n], Af[m][0], Af[m][1], Af[m][2], Af[m][3], Bh[n].x, Bh[n].y);
    }
    __syncthreads();

    float* Ds = (float*)smem;
    {
        int rq = lane >> 2, cq = (lane & 3) * 2;
#pragma unroll
        for (int m = 0; m < 2; ++m) {
            int r0 = wm * 32 + m * 16 + rq;
#pragma unroll
            for (int n = 0; n < 4; ++n) {
                int cc = (wn * 4 + n) * 8 + cq;
                *(float2*)&Ds[r0 * DS_PITCH + cc] = make_float2(c[m][n][0], c[m][n][1]);
                *(float2*)&Ds[(r0 + 8) * DS_PITCH + cc] = make_float2(c[m][n][2], c[m][n][3]);
            }
        }
    }
    __syncthreads();

    int ty = tid >> 4, tx = tid & 15;
#pragma unroll
    for (int i = 0; i < 4; ++i) {
        int er = ty * 4 + i;
        int gr = rowBase + er;
        if (gr < NN) {
            float4 va = *(const float4*)&Ds[er * DS_PITCH + tx * 4];
            float4 vb = *(const float4*)&Ds[er * DS_PITCH + 64 + tx * 4];
            __half2 a0 = __floats2half2_rn(va.x, va.y), a1 = __floats2half2_rn(va.z, va.w);
            __half2 b0 = __floats2half2_rn(vb.x, vb.y), b1 = __floats2half2_rn(vb.z, vb.w);
            *(uint2*)&Out[(size_t)gr * D + tx * 4] = make_uint2(*(uint32_t*)&a0, *(uint32_t*)&a1);
            *(uint2*)&Out[(size_t)gr * D + 64 + tx * 4] = make_uint2(*(uint32_t*)&b0, *(uint32_t*)&b1);
        }
    }
}

// ---------------- fused edge kernel v6: fp16 gathers ----------------
#define SM_SRC  0
#define SM_DST  512
#define SM_A    1024
#define SM_EDGE_TOTAL (1024 + 128 * DS_PITCH * 4)   // 70656
#define TILE 128

__global__ __launch_bounds__(512, 2)
void edge_mma_kernel(const float* __restrict__ Ef,
                     const int* __restrict__ src, const int* __restrict__ dst,
                     float* __restrict__ e_out) {
    extern __shared__ char smem[];
    uint32_t sb = smem_u32(smem);
    int tid = threadIdx.x, wid = tid >> 5, lane = tid & 31;
    int rowBase = blockIdx.x << 7;

    if (tid < 128) {
        ((int*)(smem + SM_SRC))[tid] = src[rowBase + tid];
        ((int*)(smem + SM_DST))[tid] = dst[rowBase + tid];
    }

    // convert Ef tile (128x128 f32) -> fp16 swizzled image
    {
        int row0 = wid * 8;
        int chunk = lane >> 1, half = lane & 1;
#pragma unroll
        for (int j = 0; j < 8; ++j) {
            int row = row0 + j;
            float4 v = __ldcs((const float4*)&Ef[(size_t)(rowBase + row) * D + lane * 4]);
            __half2 p0 = __halves2half2(__float2half(v.x), __float2half(v.y));
            __half2 p1 = __halves2half2(__float2half(v.z), __float2half(v.w));
            uint32_t off = (uint32_t)(row * 256 + ((chunk ^ (row & 7)) * 16) + half * 8);
            *(uint2*)(smem + SM_A + off) = make_uint2(*(uint32_t*)&p0, *(uint32_t*)&p1);
        }
    }
    __syncthreads();

    int wm = wid >> 2, wn = wid & 3;
    float c[2][4][4];
#pragma unroll
    for (int m = 0; m < 2; ++m)
#pragma unroll
        for (int n = 0; n < 4; ++n)
#pragma unroll
            for (int j = 0; j < 4; ++j) c[m][n][j] = 0.f;

    int ar = (lane & 7) + ((lane >> 3) & 1) * 8;
    int aco = lane >> 4;
    int axr = lane & 7;
    uint32_t aBase = sb + SM_A + (uint32_t)((wm * 32 + ar) * 256);

#pragma unroll
    for (int kb = 0; kb < 8; ++kb) {
        uint32_t au = (uint32_t)((2 * kb + aco) ^ axr) * 16;
        uint32_t Af[2][4];
        LDSM4(Af[0][0], Af[0][1], Af[0][2], Af[0][3], aBase + au);
        LDSM4(Af[1][0], Af[1][1], Af[1][2], Af[1][3], aBase + 16 * 256 + au);

        uint4 Bq0 = g_BfragE[kb][wn * 2 + 0][lane];
        uint4 Bq1 = g_BfragE[kb][wn * 2 + 1][lane];
#pragma unroll
        for (int m = 0; m < 2; ++m) {
            MMA16816F(c[m][0], Af[m][0], Af[m][1], Af[m][2], Af[m][3], Bq0.x, Bq0.y);
            MMA16816F(c[m][1], Af[m][0], Af[m][1], Af[m][2], Af[m][3], Bq0.z, Bq0.w);
            MMA16816F(c[m][2], Af[m][0], Af[m][1], Af[m][2], Af[m][3], Bq1.x, Bq1.y);
            MMA16816F(c[m][3], Af[m][0], Af[m][1], Af[m][2], Af[m][3], Bq1.z, Bq1.w);
        }
    }
    __syncthreads();

    float* Ds = (float*)(smem + SM_A);
    {
        int rq = lane >> 2, cq = (lane & 3) * 2;
#pragma unroll
        for (int m = 0; m < 2; ++m) {
            int r0 = wm * 32 + m * 16 + rq;
#pragma unroll
            for (int n = 0; n < 4; ++n) {
                int cc = (wn * 4 + n) * 8 + cq;
                *(float2*)&Ds[r0 * DS_PITCH + cc] = make_float2(c[m][n][0], c[m][n][1]);
                *(float2*)&Ds[(r0 + 8) * DS_PITCH + cc] = make_float2(c[m][n][2], c[m][n][3]);
            }
        }
    }
    __syncthreads();

    // ---- epilogue: fp16 gathers, coalescing-exact mapping ----
    const float isd = 0.25f;
    int ty = tid >> 4, tx = tid & 15;
    int ca = tx << 2;
    int cb = 64 + ca;
    const int* s_src = (const int*)(smem + SM_SRC);
    const int* s_dst = (const int*)(smem + SM_DST);

#pragma unroll
    for (int i = 0; i < 4; ++i) {
        int er = ty * 4 + i;
        int e = rowBase + er;
        int sn = s_src[er], dn = s_dst[er];

        const __half* Krow = g_Kh + (size_t)sn * D;
        const __half* Qrow = g_Qh + (size_t)dn * D;
        const __half* Vrow = g_Vh + (size_t)sn * D;

        uint2 ku_a = *(const uint2*)(Krow + ca), ku_b = *(const uint2*)(Krow + cb);
        uint2 qu_a = *(const uint2*)(Qrow + ca), qu_b = *(const uint2*)(Qrow + cb);

        float2 k0 = __half22float2(*(__half2*)&ku_a.x), k1 = __half22float2(*(__half2*)&ku_a.y);
        float2 k2 = __half22float2(*(__half2*)&ku_b.x), k3 = __half22float2(*(__half2*)&ku_b.y);
        float2 q0 = __half22float2(*(__half2*)&qu_a.x), q1 = __half22float2(*(__half2*)&qu_a.y);
        float2 q2 = __half22float2(*(__half2*)&qu_b.x), q3 = __half22float2(*(__half2*)&qu_b.y);

        float4 pa = *(const float4*)&Ds[er * DS_PITCH + ca];
        float4 pb = *(const float4*)&Ds[er * DS_PITCH + cb];

        float sa[4], sbv[4];
        float parta, partb;
        {
            float kq0 = fminf(fmaxf(k0.x * q0.x * isd, -5.f), 5.f);
            float kq1 = fminf(fmaxf(k0.y * q0.y * isd, -5.f), 5.f);
            float kq2 = fminf(fmaxf(k1.x * q1.x * isd, -5.f), 5.f);
            float kq3 = fminf(fmaxf(k1.y * q1.y * isd, -5.f), 5.f);
            sa[0] = kq0 * pa.x; sa[1] = kq1 * pa.y; sa[2] = kq2 * pa.z; sa[3] = kq3 * pa.w;
            parta = sa[0] + sa[1] + sa[2] + sa[3];
        }
        {
            float kq0 = fminf(fmaxf(k2.x * q2.x * isd, -5.f), 5.f);
            float kq1 = fminf(fmaxf(k2.y * q2.y * isd, -5.f), 5.f);
            float kq2 = fminf(fmaxf(k3.x * q3.x * isd, -5.f), 5.f);
            float kq3 = fminf(fmaxf(k3.y * q3.y * isd, -5.f), 5.f);
            sbv[0] = kq0 * pb.x; sbv[1] = kq1 * pb.y; sbv[2] = kq2 * pb.z; sbv[3] = kq3 * pb.w;
            partb = sbv[0] + sbv[1] + sbv[2] + sbv[3];
        }

        __stcs((float4*)&e_out[(size_t)e * D + ca], make_float4(sa[0], sa[1], sa[2], sa[3]));
        __stcs((float4*)&e_out[(size_t)e * D + cb], make_float4(sbv[0], sbv[1], sbv[2], sbv[3]));

        parta += __shfl_xor_sync(0xffffffffu, parta, 1);
        parta += __shfl_xor_sync(0xffffffffu, parta, 2);
        partb += __shfl_xor_sync(0xffffffffu, partb, 1);
        partb += __shfl_xor_sync(0xffffffffu, partb, 2);
        float s1 = __expf(fminf(fmaxf(parta, -5.f), 5.f));
        float s2 = __expf(fminf(fmaxf(partb, -5.f), 5.f));

        uint2 vu_a = *(const uint2*)(Vrow + ca), vu_b = *(const uint2*)(Vrow + cb);
        float2 v0 = __half22float2(*(__half2*)&vu_a.x), v1 = __half22float2(*(__half2*)&vu_a.y);
        float2 v2 = __half22float2(*(__half2*)&vu_b.x), v3 = __half22float2(*(__half2*)&vu_b.y);

        float* w = &g_wV[dn * D + ca];
        asm volatile("red.global.add.v4.f32 [%0], {%1,%2,%3,%4};"
                     :: "l"(w), "f"(v0.x * s1), "f"(v0.y * s1), "f"(v1.x * s1), "f"(v1.y * s1)
                     : "memory");
        asm volatile("red.global.add.v4.f32 [%0], {%1,%2,%3,%4};"
                     :: "l"(w + 64), "f"(v2.x * s2), "f"(v2.y * s2), "f"(v3.x * s2), "f"(v3.y * s2)
                     : "memory");
        if ((tx & 3) == 0) {
            atomicAdd(&g_z[dn * H + (tx >> 2)], s1);
            atomicAdd(&g_z[dn * H + 4 + (tx >> 2)], s2);
        }
    }
}

// ---------------- normalize (float4) ----------------
__global__ __launch_bounds__(512)
void norm_kernel(float* __restrict__ h_out) {
    int i = blockIdx.x * blockDim.x + threadIdx.x;   // float4 index
    if (i < NN * D / 4) {
        int base = i * 4;
        int n = base >> 7;
        int hh = (base & 127) >> 4;
        float z = g_z[n * H + hh] + 1e-6f;
        float4 wv = ((const float4*)g_wV)[i];
        ((float4*)h_out)[i] = make_float4(wv.x / z, wv.y / z, wv.z / z, wv.w / z);
    }
}

// ---------------- launch ----------------
extern "C" void kernel_launch(void* const* d_in, const int* in_sizes, int n_in,
                              void* d_out, int out_size) {
    const float* node_feats = (const float*)d_in[0];
    const float* edge_feats = (const float*)d_in[1];
    const int* src = (const int*)d_in[2];
    const int* dst = (const int*)d_in[3];
    const float* WQ = (const float*)d_in[4];
    const float* WK = (const float*)d_in[5];
    const float* WV = (const float*)d_in[6];
    const float* We = (const float*)d_in[7];

    float* out = (float*)d_out;
    float* h_out = out;                  // [NN, H, DH]
    float* e_out = out + (size_t)NN * D; // [NE, H, DH]

    static int smem_set = 0;
    if (!smem_set) {
        cudaFuncSetAttribute(edge_mma_kernel, cudaFuncAttributeMaxDynamicSharedMemorySize, SM_EDGE_TOTAL);
        cudaFuncSetAttribute(node_mma_kernel, cudaFuncAttributeMaxDynamicSharedMemorySize, SM_NODE_TOTAL);
        smem_set = 1;
    }

    setup_kernel<<<(NN * D / 4 + 511) / 512, 512>>>(WQ, WK, WV, We);

    dim3 gn((NN + 127) / 128, 3);
    node_mma_kernel<<<gn, 512, SM_NODE_TOTAL>>>(node_feats);

    edge_mma_kernel<<<NE / TILE, 512, SM_EDGE_TOTAL>>>(edge_feats, src, dst, e_out);

    norm_kernel<<<(NN * D / 4 + 511) / 512, 512>>>(h_out);
}